// round 12
// baseline (speedup 1.0000x reference)
#include <cuda_runtime.h>

// float32(3.4 * 3.4), exactly jnp.float32(RADIUS * RADIUS)
#define RADIUS2 11.559999465942383f
#define NSAMPLE 5
#define NBATCH  8
#define STAGE   64          // candidates staged in shared for phase 1
#define TPB     256
#define ROWS_PER_BLOCK (TPB / 4)

__device__ __forceinline__ float sq3(float x0, float x1, float x2) {
    return __fadd_rn(__fadd_rn(__fmul_rn(x0, x0), __fmul_rn(x1, x1)),
                     __fmul_rn(x2, x2));
}

__device__ __forceinline__ float dist2(float qx, float qy, float qz, float sqq,
                                       float bx, float by, float bz, float sqk) {
    float dot = __fmaf_rn(qz, bz, __fmaf_rn(qy, by, __fmul_rn(qx, bx)));
    return __fsub_rn(__fadd_rn(sqq, sqk), __fmul_rn(2.0f, dot));
}

// Phase 1: FOUR threads per row (a quad of adjacent lanes). Thread h of the
// quad evaluates staged candidates [16h, 16h+16) into a 16-bit mask. Two
// shfl_xor merges rebuild the 64-bit ascending-k mask on the quad leader,
// which extracts the first NSAMPLE hits.
// Phase 2: rows with <NSAMPLE staged hits are rescued warp-per-row with an
// early-exiting ballot scan from k=0.
__global__ void __launch_bounds__(TPB)
ball_query_quad_kernel(const float* __restrict__ x,  // [B,N,3]
                       float* __restrict__ out,      // [B,N,5]
                       int n_rows, int npb)
{
    __shared__ float4 s_pts[STAGE];
    __shared__ int    s_fail[ROWS_PER_BLOCK];
    __shared__ int    s_nfail;

    int row0  = blockIdx.x * ROWS_PER_BLOCK;
    int half  = threadIdx.x & 3;                 // which 16 candidates
    int row   = row0 + (threadIdx.x >> 2);
    int lane  = threadIdx.x & 31;
    int wid   = threadIdx.x >> 5;
    int nwarps = TPB >> 5;

    if (threadIdx.x == 0) s_nfail = 0;

    // Block-uniform batch check.
    int last_row = min(row0 + ROWS_PER_BLOCK - 1, n_rows - 1);
    int b0 = row0 / npb;
    bool uniform = (b0 == last_row / npb) && (npb >= STAGE);

    if (uniform && threadIdx.x < STAGE) {
        const float* xb0 = x + (long long)b0 * npb * 3;
        int j = threadIdx.x;
        float bx = xb0[j * 3 + 0];
        float by = xb0[j * 3 + 1];
        float bz = xb0[j * 3 + 2];
        s_pts[j] = make_float4(bx, by, bz, sq3(bx, by, bz));
    }
    __syncthreads();

    // ---------- Phase 1 ----------
    {
        int rr = min(row, n_rows - 1);           // clamp; real guard at output
        int q = rr - b0 * npb;                   // uniform => batch is b0
        const float* xb = x + (long long)b0 * npb * 3;

        unsigned m = 0u;
        if (uniform) {
            float qx = xb[q * 3 + 0];
            float qy = xb[q * 3 + 1];
            float qz = xb[q * 3 + 2];
            float sqq = sq3(qx, qy, qz);
            int j0 = half * 16;
            #pragma unroll
            for (int j = 0; j < 16; j++) {
                float4 p = s_pts[j0 + j];
                float d2 = dist2(qx, qy, qz, sqq, p.x, p.y, p.z, p.w);
                m |= (d2 < RADIUS2) ? (1u << j) : 0u;
            }
        }

        // Merge quad: step 1 pairs halves {0,1} and {2,3} into 32-bit masks
        // on even-half threads; step 2 joins the two 32-bit masks on half 0.
        unsigned p1 = __shfl_xor_sync(0xffffffffu, m, 1);
        unsigned pair32 = m | (p1 << 16);        // valid on half 0 and half 2
        unsigned hi32 = __shfl_xor_sync(0xffffffffu, pair32, 2);

        if (half == 0 && row < n_rows) {
            unsigned long long mask = (unsigned long long)pair32 |
                                      ((unsigned long long)hi32 << 32);
            if (__popcll(mask) >= NSAMPLE) {
                unsigned long long t = mask;
                int i0 = __ffsll(t) - 1; t &= t - 1;
                int i1 = __ffsll(t) - 1; t &= t - 1;
                int i2 = __ffsll(t) - 1; t &= t - 1;
                int i3 = __ffsll(t) - 1; t &= t - 1;
                int i4 = __ffsll(t) - 1;
                float* o = out + (long long)row * NSAMPLE;
                o[0] = (float)i0; o[1] = (float)i1; o[2] = (float)i2;
                o[3] = (float)i3; o[4] = (float)i4;
            } else {
                int slot = atomicAdd(&s_nfail, 1);
                s_fail[slot] = row;
            }
        }
    }
    __syncthreads();

    // ---------- Phase 2: warp-per-failed-row, early-exit ballot scan --------
    int nf = s_nfail;
    for (int i = wid; i < nf; i += nwarps) {
        int frow = s_fail[i];
        int b = frow / npb;                      // rare path: division OK
        int q = frow - b * npb;
        const float* xb = x + (long long)b * npb * 3;

        float qx = xb[q * 3 + 0];
        float qy = xb[q * 3 + 1];
        float qz = xb[q * 3 + 2];
        float sqq = sq3(qx, qy, qz);

        int i0 = 0, i1 = 0, i2 = 0, i3 = 0, i4 = 0;
        int cnt = 0;

        for (int base = 0; base < npb; base += 32) {
            int k = base + lane;
            bool pred = false;
            if (k < npb) {
                float bx = xb[k * 3 + 0];
                float by = xb[k * 3 + 1];
                float bz = xb[k * 3 + 2];
                float d2 = dist2(qx, qy, qz, sqq, bx, by, bz, sq3(bx, by, bz));
                pred = (d2 < RADIUS2);
            }
            unsigned mm = __ballot_sync(0xffffffffu, pred);
            while (mm && cnt < NSAMPLE) {
                int idx = base + __ffs(mm) - 1;
                mm &= mm - 1;
                if (cnt == 0) {
                    i0 = idx; i1 = idx; i2 = idx; i3 = idx; i4 = idx;
                } else if (cnt == 1) { i1 = idx;
                } else if (cnt == 2) { i2 = idx;
                } else if (cnt == 3) { i3 = idx;
                } else               { i4 = idx; }
                cnt++;
            }
            if (cnt == NSAMPLE) break;
        }

        if (lane == 0) {
            float* o = out + (long long)frow * NSAMPLE;
            o[0] = (float)i0; o[1] = (float)i1; o[2] = (float)i2;
            o[3] = (float)i3; o[4] = (float)i4;
        }
    }
}

extern "C" void kernel_launch(void* const* d_in, const int* in_sizes, int n_in,
                              void* d_out, int out_size) {
    const float* x = (const float*)d_in[0];
    float* out = (float*)d_out;

    int n_rows = out_size / NSAMPLE;       // B * N query rows
    int total_pts = in_sizes[0] / 3;       // B * N points
    int npb = total_pts / NBATCH;          // N per batch

    int blocks = (n_rows + ROWS_PER_BLOCK - 1) / ROWS_PER_BLOCK;
    ball_query_quad_kernel<<<blocks, TPB>>>(x, out, n_rows, npb);
}

// round 13
// speedup vs baseline: 1.2097x; 1.2097x over previous
#include <cuda_runtime.h>

// float32(3.4 * 3.4), exactly jnp.float32(RADIUS * RADIUS)
#define RADIUS2 11.559999465942383f
#define NSAMPLE 5
#define NBATCH  8
#define STAGE   64          // candidates staged in shared for phase 1
#define TPB     256
#define ROWS_PER_BLOCK (TPB / 2)

__device__ __forceinline__ float sq3(float x0, float x1, float x2) {
    return __fadd_rn(__fadd_rn(__fmul_rn(x0, x0), __fmul_rn(x1, x1)),
                     __fmul_rn(x2, x2));
}

__device__ __forceinline__ float dist2(float qx, float qy, float qz, float sqq,
                                       float bx, float by, float bz, float sqk) {
    float dot = __fmaf_rn(qz, bz, __fmaf_rn(qy, by, __fmul_rn(qx, bx)));
    return __fsub_rn(__fadd_rn(sqq, sqk), __fmul_rn(2.0f, dot));
}

// Phase 1 (R11 layout — best measured): TWO threads per row; each evaluates
// 32 of the 64 staged candidates; shfl_xor(1) merges on the even lane.
// Phase 2: warp-per-failed-row rescue, 128 candidates per iteration
// (4 groups x 32, independent loads + 4 pipelined ballots), early exit.
__global__ void __launch_bounds__(TPB)
ball_query_pair4_kernel(const float* __restrict__ x,  // [B,N,3]
                        float* __restrict__ out,      // [B,N,5]
                        int n_rows, int npb)
{
    __shared__ float4 s_pts[STAGE];
    __shared__ int    s_fail[ROWS_PER_BLOCK];
    __shared__ int    s_nfail;

    int row0  = blockIdx.x * ROWS_PER_BLOCK;
    int half  = threadIdx.x & 1;
    int row   = row0 + (threadIdx.x >> 1);
    int lane  = threadIdx.x & 31;
    int wid   = threadIdx.x >> 5;
    int nwarps = TPB >> 5;

    if (threadIdx.x == 0) s_nfail = 0;

    int last_row = min(row0 + ROWS_PER_BLOCK - 1, n_rows - 1);
    int b0 = row0 / npb;
    bool uniform = (b0 == last_row / npb) && (npb >= STAGE);

    if (uniform && threadIdx.x < STAGE) {
        const float* xb0 = x + (long long)b0 * npb * 3;
        int j = threadIdx.x;
        float bx = xb0[j * 3 + 0];
        float by = xb0[j * 3 + 1];
        float bz = xb0[j * 3 + 2];
        s_pts[j] = make_float4(bx, by, bz, sq3(bx, by, bz));
    }
    __syncthreads();

    // ---------- Phase 1 ----------
    {
        int rr = min(row, n_rows - 1);
        int q = rr - b0 * npb;                   // uniform => batch is b0
        const float* xb = x + (long long)b0 * npb * 3;

        unsigned m = 0u;
        if (uniform) {
            float qx = xb[q * 3 + 0];
            float qy = xb[q * 3 + 1];
            float qz = xb[q * 3 + 2];
            float sqq = sq3(qx, qy, qz);
            int j0 = half * 32;
            #pragma unroll
            for (int j = 0; j < 32; j++) {
                float4 p = s_pts[j0 + j];
                float d2 = dist2(qx, qy, qz, sqq, p.x, p.y, p.z, p.w);
                m |= (d2 < RADIUS2) ? (1u << j) : 0u;
            }
        }

        unsigned other = __shfl_xor_sync(0xffffffffu, m, 1);

        if (half == 0 && row < n_rows) {
            unsigned long long mask = (unsigned long long)m |
                                      ((unsigned long long)other << 32);
            if (__popcll(mask) >= NSAMPLE) {
                unsigned long long t = mask;
                int i0 = __ffsll(t) - 1; t &= t - 1;
                int i1 = __ffsll(t) - 1; t &= t - 1;
                int i2 = __ffsll(t) - 1; t &= t - 1;
                int i3 = __ffsll(t) - 1; t &= t - 1;
                int i4 = __ffsll(t) - 1;
                float* o = out + (long long)row * NSAMPLE;
                o[0] = (float)i0; o[1] = (float)i1; o[2] = (float)i2;
                o[3] = (float)i3; o[4] = (float)i4;
            } else {
                int slot = atomicAdd(&s_nfail, 1);
                s_fail[slot] = row;
            }
        }
    }
    __syncthreads();

    // ---------- Phase 2: warp-per-failed-row, 128 candidates / iteration ----
    int nf = s_nfail;
    for (int i = wid; i < nf; i += nwarps) {
        int frow = s_fail[i];
        int b = frow / npb;
        int q = frow - b * npb;
        const float* xb = x + (long long)b * npb * 3;

        float qx = xb[q * 3 + 0];
        float qy = xb[q * 3 + 1];
        float qz = xb[q * 3 + 2];
        float sqq = sq3(qx, qy, qz);

        int i0 = 0, i1 = 0, i2 = 0, i3 = 0, i4 = 0;
        int cnt = 0;

        for (int base = 0; base < npb; base += 128) {
            // Evaluate 4 independent 32-candidate groups; loads overlap.
            unsigned mm[4];
            #pragma unroll
            for (int g = 0; g < 4; g++) {
                int k = base + g * 32 + lane;
                bool pred = false;
                if (k < npb) {
                    float bx = xb[k * 3 + 0];
                    float by = xb[k * 3 + 1];
                    float bz = xb[k * 3 + 2];
                    float d2 = dist2(qx, qy, qz, sqq, bx, by, bz,
                                     sq3(bx, by, bz));
                    pred = (d2 < RADIUS2);
                }
                mm[g] = __ballot_sync(0xffffffffu, pred);
            }

            #pragma unroll
            for (int g = 0; g < 4; g++) {
                unsigned w = mm[g];
                int gb = base + g * 32;
                while (w && cnt < NSAMPLE) {
                    int idx = gb + __ffs(w) - 1;
                    w &= w - 1;
                    if (cnt == 0) {
                        i0 = idx; i1 = idx; i2 = idx; i3 = idx; i4 = idx;
                    } else if (cnt == 1) { i1 = idx;
                    } else if (cnt == 2) { i2 = idx;
                    } else if (cnt == 3) { i3 = idx;
                    } else               { i4 = idx; }
                    cnt++;
                }
            }
            if (cnt == NSAMPLE) break;
        }

        if (lane == 0) {
            float* o = out + (long long)frow * NSAMPLE;
            o[0] = (float)i0; o[1] = (float)i1; o[2] = (float)i2;
            o[3] = (float)i3; o[4] = (float)i4;
        }
    }
}

extern "C" void kernel_launch(void* const* d_in, const int* in_sizes, int n_in,
                              void* d_out, int out_size) {
    const float* x = (const float*)d_in[0];
    float* out = (float*)d_out;

    int n_rows = out_size / NSAMPLE;       // B * N query rows
    int total_pts = in_sizes[0] / 3;       // B * N points
    int npb = total_pts / NBATCH;          // N per batch

    int blocks = (n_rows + ROWS_PER_BLOCK - 1) / ROWS_PER_BLOCK;
    ball_query_pair4_kernel<<<blocks, TPB>>>(x, out, n_rows, npb);
}